// round 17
// baseline (speedup 1.0000x reference)
#include <cuda_runtime.h>
#include <math.h>

// ---------------------------------------------------------------------------
// Problem constants
// ---------------------------------------------------------------------------
#define B_   2
#define P_   4000
#define NP_  4096
#define D_   64
#define M_   512
#define HW_  214272
#define BITW (HW_ / 32)           // 6696

#define S0_   ((size_t)B_ * 128 * HW_)
#define S2_   ((size_t)B_ * 64 * HW_)
#define OFF1_ (S0_)
#define OFF2_ (2 * S0_)
#define OFF3_ (2 * S0_ + S2_)
#define OFF4_ (OFF3_ + (size_t)B_ * P_ * D_)

// Tiling (R2/R14 lineage)
#define TILE_P 64
#define TILE_T 128
#define PITCH  68        // 272 B rows; conflict-free LDS.128, 16B aligned
#define NTHR   256
#define PTILES 63                       // ceil(4000/64)
#define NB_PT  (PTILES * B_)            // 126 pillar tiles per branch
#define CPTS   2048                     // points per chunk
#define N_PTI  (NB_PT * 2)              // 252 point-chunk items
#define N_MEMI NB_PT                    // 126 memory items
#define N_ATTI (N_PTI + N_MEMI)         // 378 attention items
#define NB_F   296                      // fill blocks
#define NB_TOT (N_ATTI + NB_F)          // 674

#define PLANE4 (HW_ / 4)                // 53568 float4 per plane
#define QUART4 (PLANE4 / 4)             // 13392 float4 per chunk
#define NCHUNK (640 * 4)                // 2560 chunks total

// dynamic shared layout (bytes) -- attention role; fill role uses first 53568B
#define SM_PL   0                                   // 64*68*4      = 17408
#define SM_PT   17408                               // 2*128*68*4   = 69632
#define SM_TKV  87040                               // 64*8*4       =  2048
#define SM_TKI  89088                               // 64*8*4       =  2048
#define SMEM_BYTES 91136

__device__ int      g_winner[B_ * HW_];
__device__ unsigned g_bitmap[B_ * BITW];
__device__ float    g_pkv[B_ * P_ * 16];   // point: 2 chunks x 8 candidates
__device__ int      g_pki[B_ * P_ * 16];

// ---------------------------------------------------------------------------
__device__ __forceinline__ void cp16(void* dst, const void* src) {
    unsigned a = (unsigned)__cvta_generic_to_shared(dst);
    asm volatile("cp.async.cg.shared.global [%0], [%1], 16;" :: "r"(a), "l"(src));
}
__device__ __forceinline__ void cp_commit() {
    asm volatile("cp.async.commit_group;" ::: "memory");
}
__device__ __forceinline__ void cp_wait_all() {
    asm volatile("cp.async.wait_group 0;" ::: "memory");
}
__device__ __forceinline__ void fma2(unsigned long long& acc,
                                     unsigned long long a, unsigned long long b) {
    asm volatile("fma.rn.f32x2 %0, %1, %2, %0;" : "+l"(acc) : "l"(a), "l"(b));
}
__device__ __forceinline__ float pair_sum(unsigned long long v) {
    return __uint_as_float((unsigned)v) + __uint_as_float((unsigned)(v >> 32));
}

// ---------------------------------------------------------------------------
// Attention core (R2/R14): 64 pillars x npts -> per-pillar top-8 in
// s_tkv/s_tki. Candidate indices recorded relative to idx_base.
// ---------------------------------------------------------------------------
__device__ void attn_core(const float* __restrict__ pb,
                          const float* __restrict__ vb,
                          int npts, int idx_base, int pvalid, char* smem)
{
    float* s_pl  = (float*)(smem + SM_PL);
    float* s_pt  = (float*)(smem + SM_PT);
    float* s_tkv = (float*)(smem + SM_TKV);
    int*   s_tki = (int*)(smem + SM_TKI);

    const int t  = threadIdx.x;
    const int tx = t & 31;
    const int wy = t >> 5;
    const unsigned FULL = 0xffffffffu;

    s_tkv[t]       = -INFINITY;
    s_tkv[t + 256] = -INFINITY;

#pragma unroll
    for (int q = 0; q < 8; ++q) {
        int lin = t + q * NTHR;
        int r = lin >> 4, c = (lin & 15) << 2;
        cp16(s_pt + r * PITCH + c, vb + r * D_ + c);
    }
    cp_commit();

#pragma unroll
    for (int q = 0; q < 4; ++q) {
        int lin = t + q * NTHR;
        int r = lin >> 4, c = (lin & 15) << 2;
        float4 v = make_float4(0.f, 0.f, 0.f, 0.f);
        if (r < pvalid) v = *(const float4*)(pb + r * D_ + c);
        *(float4*)(s_pl + r * PITCH + c) = v;
    }
    __syncthreads();

    float vmin[8];
#pragma unroll
    for (int i = 0; i < 8; ++i) vmin[i] = -INFINITY;

    const int NT = npts / TILE_T;
    for (int tile = 0; tile < NT; ++tile) {
        float* buf = s_pt + (tile & 1) * (TILE_T * PITCH);
        cp_wait_all();
        __syncthreads();
        if (tile + 1 < NT) {
            float* nb = s_pt + ((tile + 1) & 1) * (TILE_T * PITCH);
            const float* src = vb + (size_t)(tile + 1) * TILE_T * D_;
#pragma unroll
            for (int q = 0; q < 8; ++q) {
                int lin = t + q * NTHR;
                int r = lin >> 4, c = (lin & 15) << 2;
                cp16(nb + r * PITCH + c, src + r * D_ + c);
            }
            cp_commit();
        }

        unsigned long long acc[8][4];
#pragma unroll
        for (int i = 0; i < 8; ++i)
#pragma unroll
            for (int j = 0; j < 4; ++j) acc[i][j] = 0ull;

#pragma unroll
        for (int dc = 0; dc < D_; dc += 4) {
            unsigned long long a0[8], a1[8], x0[4], x1[4];
#pragma unroll
            for (int i = 0; i < 8; ++i) {
                ulonglong2 v = *(const ulonglong2*)(s_pl + ((wy << 3) + i) * PITCH + dc);
                a0[i] = v.x; a1[i] = v.y;
            }
#pragma unroll
            for (int j = 0; j < 4; ++j) {
                ulonglong2 v = *(const ulonglong2*)(buf + (tx + 32 * j) * PITCH + dc);
                x0[j] = v.x; x1[j] = v.y;
            }
#pragma unroll
            for (int i = 0; i < 8; ++i)
#pragma unroll
                for (int j = 0; j < 4; ++j) {
                    fma2(acc[i][j], a0[i], x0[j]);
                    fma2(acc[i][j], a1[i], x1[j]);
                }
        }

        // ---- top-8 maintenance: one batched ballot per tile ----
        const int base = idx_base + tile * TILE_T;
        bool anyhit = false;
#pragma unroll
        for (int i = 0; i < 8; ++i) {
            float thr = vmin[i];
#pragma unroll
            for (int j = 0; j < 4; ++j)
                anyhit |= (pair_sum(acc[i][j]) > thr);
        }
        if (__ballot_sync(FULL, anyhit)) {
#pragma unroll
            for (int i = 0; i < 8; ++i) {
                const int pr = (wy << 3) + i;
                float thr = vmin[i];
                float s[4];
#pragma unroll
                for (int j = 0; j < 4; ++j) s[j] = pair_sum(acc[i][j]);
                unsigned any = __ballot_sync(FULL,
                    (s[0] > thr) | (s[1] > thr) | (s[2] > thr) | (s[3] > thr));
                if (any) {
                    float* tv = s_tkv + pr * 8;
                    int*   ti = s_tki + pr * 8;
#pragma unroll
                    for (int j = 0; j < 4; ++j) {
                        unsigned m = __ballot_sync(FULL, s[j] > thr);
                        while (m) {
                            int ln = __ffs(m) - 1; m &= m - 1;
                            float v = __shfl_sync(FULL, s[j], ln);
                            if (v > thr) {
                                int slot = 0; float mn = tv[0];
#pragma unroll
                                for (int k = 1; k < 8; ++k) {
                                    float x = tv[k];
                                    if (x < mn) { mn = x; slot = k; }
                                }
                                tv[slot] = v;
                                ti[slot] = base + ln + 32 * j;
                                thr = tv[0];
#pragma unroll
                                for (int k = 1; k < 8; ++k) thr = fminf(thr, tv[k]);
                            }
                        }
                    }
                    vmin[i] = thr;
                }
            }
        }
    }
    __syncwarp();
}

// ---------------------------------------------------------------------------
// Fill role (verified R13/R14): chunk-structured, winner-materialized static
// planes; upper planes zeroed skipping winner columns (epilogues own those).
// ---------------------------------------------------------------------------
__device__ void fill_role(int fid, const float* __restrict__ pillars,
                          const float* __restrict__ scale,
                          float* __restrict__ out, char* smem)
{
    unsigned* s_bm = (unsigned*)smem;
    const int t = threadIdx.x;
    for (int i = t; i < B_ * BITW; i += NTHR) s_bm[i] = g_bitmap[i];
    __syncthreads();

    const float4 z = make_float4(0.f, 0.f, 0.f, 0.f);

    for (int c = fid; c < NCHUNK; c += NB_F) {
        const int plane = c >> 2;
        const int q0 = (c & 3) * QUART4;
        float4* __restrict__ dst = (float4*)out + (size_t)plane * PLANE4;

        int b, ch;
        const float* src;
        bool stat;
        if (plane < 512) {
            int pl = plane & 255;
            b = pl >> 7; ch = pl & 127;
            stat = ch < 64; src = pillars;
        } else {
            int pl = plane - 512;
            b = pl >> 6; ch = pl & 63;
            stat = true; src = scale;
        }

        const unsigned* bm = s_bm + b * BITW;
        if (!stat) {
            for (int f = q0 + t; f < q0 + QUART4; f += NTHR) {
                unsigned bits = (bm[f >> 3] >> ((f & 7) * 4)) & 0xFu;
                if (!bits) {
                    __stcs(dst + f, z);
                } else {
                    float* d = (float*)(dst + f);
                    if (!(bits & 1u)) d[0] = 0.f;
                    if (!(bits & 2u)) d[1] = 0.f;
                    if (!(bits & 4u)) d[2] = 0.f;
                    if (!(bits & 8u)) d[3] = 0.f;
                }
            }
        } else {
            const int* win = g_winner + b * HW_;
            const float* sp = src + (size_t)b * P_ * D_ + ch;
            for (int f = q0 + t; f < q0 + QUART4; f += NTHR) {
                float4 v = z;
                unsigned bits = (bm[f >> 3] >> ((f & 7) * 4)) & 0xFu;
                if (bits) {
                    int col = f << 2;
                    if (bits & 1u) v.x = sp[(size_t)win[col]     * D_];
                    if (bits & 2u) v.y = sp[(size_t)win[col + 1] * D_];
                    if (bits & 4u) v.z = sp[(size_t)win[col + 2] * D_];
                    if (bits & 8u) v.w = sp[(size_t)win[col + 3] * D_];
                }
                __stcs(dst + f, v);
            }
        }
    }
}

// ---------------------------------------------------------------------------
// Fused kernel. Interleave: bid<592: even -> attn item bid/2, odd -> fill
// bid/2; bid in [592,674): attn item 296+(bid-592).
// Attention items: [0,252) point chunks (chunk-major), [252,378) memory.
// Point chunks write partial top-8 to scratch; memory items keep the full
// in-kernel epilogue (softmax + gather + out4 + out0-upper winner scatter).
// ---------------------------------------------------------------------------
__global__ void __launch_bounds__(NTHR, 2)
fused_kernel(const float* __restrict__ pillars,
             const float* __restrict__ scale,
             const float* __restrict__ points,
             const float* __restrict__ W,
             const int* __restrict__ idx,
             float* __restrict__ out)
{
    extern __shared__ char smem[];
    const int bid = blockIdx.x;
    int aid;
    if (bid < 2 * NB_F) {
        if (bid & 1) { fill_role(bid >> 1, pillars, scale, out, smem); return; }
        aid = bid >> 1;
    } else {
        aid = NB_F + (bid - 2 * NB_F);
    }

    float* s_tkv = (float*)(smem + SM_TKV);
    int*   s_tki = (int*)(smem + SM_TKI);
    const int t  = threadIdx.x;
    const int tx = t & 31;
    const int wy = t >> 5;

    if (aid < N_PTI) {
        // ---- point chunk: partial top-8 -> scratch
        const int chunk = aid / NB_PT;              // 0 or 1
        const int pid   = aid % NB_PT;
        const int b     = pid / PTILES;
        const int p0    = (pid % PTILES) * TILE_P;
        const int pvalid = min(TILE_P, P_ - p0);
        const float* pb = pillars + ((size_t)b * P_ + p0) * D_;
        const float* vb = points + ((size_t)b * NP_ + (size_t)chunk * CPTS) * D_;
        attn_core(pb, vb, CPTS, chunk * CPTS, pvalid, smem);

        const int bp0 = b * P_ + p0;
#pragma unroll 1
        for (int i = 0; i < 8; ++i) {
            const int pr = (wy << 3) + i;
            if (pr >= pvalid) break;
            if (tx < 8) {
                g_pkv[(size_t)(bp0 + pr) * 16 + chunk * 8 + tx] = s_tkv[pr * 8 + tx];
                g_pki[(size_t)(bp0 + pr) * 16 + chunk * 8 + tx] = s_tki[pr * 8 + tx];
            }
        }
    } else {
        // ---- memory item: full epilogue (out4 dense + out0-upper scatter)
        const int mid = aid - N_PTI;
        const int b   = mid / PTILES;
        const int p0  = (mid % PTILES) * TILE_P;
        const int pvalid = min(TILE_P, P_ - p0);
        const float* pb = pillars + ((size_t)b * P_ + p0) * D_;
        attn_core(pb, W, M_, 0, pvalid, smem);

#pragma unroll 1
        for (int i = 0; i < 8; ++i) {
            const int pr = (wy << 3) + i;
            if (pr >= pvalid) break;
            float vals[8]; int id8[8];
#pragma unroll
            for (int k = 0; k < 8; ++k) {
                vals[k] = s_tkv[pr * 8 + k]; id8[k] = s_tki[pr * 8 + k];
            }
            float mx = vals[0];
#pragma unroll
            for (int k = 1; k < 8; ++k) mx = fmaxf(mx, vals[k]);
            float w[8], ssum = 0.f;
#pragma unroll
            for (int k = 0; k < 8; ++k) { w[k] = expf(vals[k] - mx); ssum += w[k]; }
            float inv = 1.f / ssum;
            float a0 = 0.f, a1 = 0.f;
#pragma unroll
            for (int k = 0; k < 8; ++k) {
                const float* vp = W + (size_t)id8[k] * D_;
                float wk = w[k] * inv;
                a0 += wk * vp[tx];
                a1 += wk * vp[tx + 32];
            }
            const int p = p0 + pr;
            float* op = out + OFF4_ + ((size_t)b * P_ + p) * D_;
            op[tx] = a0;
            op[tx + 32] = a1;

            const int col = idx[b * P_ + p];
            if (g_winner[b * HW_ + col] == p) {
                size_t g0 = (size_t)b * 128 * HW_ + (size_t)(64 + tx) * HW_ + col;
                out[g0] = a0;                        // out0 upper
                out[g0 + (size_t)32 * HW_] = a1;
            }
        }
    }
}

// ---------------------------------------------------------------------------
// Merge: one warp per pillar. Merge 2x8 candidates -> top-8, softmax, gather
// from points; write dense pos_point (out3) and winner scatter to out1 upper.
// ---------------------------------------------------------------------------
__global__ void __launch_bounds__(256)
merge_kernel(const float* __restrict__ points, const int* __restrict__ idx,
             float* __restrict__ out)
{
    const int bp = blockIdx.x * 8 + (threadIdx.x >> 5);
    const int tx = threadIdx.x & 31;
    if (bp >= B_ * P_) return;
    const unsigned FULL = 0xffffffffu;
    const int b = bp / P_;
    const float* vb = points + (size_t)b * NP_ * D_;

    float v = (tx < 16) ? g_pkv[(size_t)bp * 16 + tx] : -INFINITY;
    int   ii = (tx < 16) ? g_pki[(size_t)bp * 16 + tx] : 0;

    float vals[8]; int ids[8];
#pragma unroll
    for (int k = 0; k < 8; ++k) {
        float m = v;
#pragma unroll
        for (int off = 16; off; off >>= 1)
            m = fmaxf(m, __shfl_xor_sync(FULL, m, off));
        unsigned ball = __ballot_sync(FULL, v == m);
        int sel = __ffs(ball) - 1;
        ids[k] = __shfl_sync(FULL, ii, sel);
        vals[k] = m;
        if (tx == sel) v = -INFINITY;
    }

    float mx = vals[0];
#pragma unroll
    for (int k = 1; k < 8; ++k) mx = fmaxf(mx, vals[k]);
    float wt[8], ssum = 0.f;
#pragma unroll
    for (int k = 0; k < 8; ++k) { wt[k] = expf(vals[k] - mx); ssum += wt[k]; }
    float inv = 1.f / ssum;
    float a0 = 0.f, a1 = 0.f;
#pragma unroll
    for (int k = 0; k < 8; ++k) {
        const float* vp = vb + (size_t)ids[k] * D_;
        float wk = wt[k] * inv;
        a0 += wk * vp[tx];
        a1 += wk * vp[tx + 32];
    }
    float* op = out + OFF3_ + (size_t)bp * D_;
    op[tx] = a0;
    op[tx + 32] = a1;

    const int p = bp - b * P_;
    const int col = idx[bp];
    if (g_winner[b * HW_ + col] == p) {
        size_t g0 = (size_t)b * 128 * HW_ + (size_t)(64 + tx) * HW_ + col;
        out[OFF1_ + g0] = a0;                        // out1 upper
        out[OFF1_ + g0 + (size_t)32 * HW_] = a1;
    }
}

// ---------------------------------------------------------------------------
__global__ void pre1_kernel() {
    int i = blockIdx.x * blockDim.x + threadIdx.x;
    int4* w4 = (int4*)g_winner;
    if (i < (B_ * HW_) / 4) w4[i] = make_int4(-1, -1, -1, -1);
    if (i < B_ * BITW) g_bitmap[i] = 0u;
}
__global__ void pre2_kernel(const int* __restrict__ idx) {
    int i = blockIdx.x * blockDim.x + threadIdx.x;
    if (i < B_ * P_) {
        int b = i / P_;
        int col = idx[i];
        atomicMax(&g_winner[b * HW_ + col], i - b * P_);
        atomicOr(&g_bitmap[b * BITW + (col >> 5)], 1u << (col & 31));
    }
}

// ---------------------------------------------------------------------------
extern "C" void kernel_launch(void* const* d_in, const int* in_sizes, int n_in,
                              void* d_out, int out_size) {
    (void)in_sizes; (void)n_in; (void)out_size;
    const float* pillars = (const float*)d_in[0];
    const float* scale   = (const float*)d_in[1];
    const float* points  = (const float*)d_in[2];
    const float* W       = (const float*)d_in[3];
    const int*   idx     = (const int*)d_in[4];
    float* out = (float*)d_out;

    cudaFuncSetAttribute(fused_kernel,
                         cudaFuncAttributeMaxDynamicSharedMemorySize, SMEM_BYTES);

    pre1_kernel<<<(B_ * HW_ / 4 + 255) / 256, 256>>>();
    pre2_kernel<<<(B_ * P_ + 255) / 256, 256>>>(idx);
    fused_kernel<<<NB_TOT, NTHR, SMEM_BYTES>>>(pillars, scale, points, W, idx, out);
    merge_kernel<<<(B_ * P_ + 7) / 8, 256>>>(points, idx, out);
}